// round 11
// baseline (speedup 1.0000x reference)
#include <cuda_runtime.h>

// rate_RNN_mante: T=1000 sequential steps, B=64, IN=4, H=512, OUT=3.
// Wr = (l*pin) @ pout^T is rank-2 -> only two H-wide reductions (s0,s1) per
// step sit on the serial dependence chain.
//
// WARP-SPECIALIZED: one CTA per batch, 8 warps.
//   warps 4..7 (high wid = high arbiter priority): recurrence. 128 threads x
//     4 hidden units. Per step they execute ONLY: tanh chain, po-products,
//     8 shuffles, STS r + s-partials, barrier, 4 LDS + add tree. The next
//     step's acc = lm*M + Win.x FMAs are issued inside the shuffle-latency
//     shadow (pre-barrier).
//   warps 0..3: y = Wout @ tanh(mem). Read r from double-buffered smem after
//     the barrier, reduce (products + 12 shuffles + helpers-only named
//     barrier), STG final y directly. Entirely off the critical path; no
//     finalize kernel, no global scratch.
// tanh = 1 - 2/(2^M+1) with state pre-scaled by 2*log2(e) (EX2+RCP, ~1e-7).

#define TSTEPS 1000
#define BATCH  64
#define HID    512
#define OUTDIM 3
#define NTHR   256          // 8 warps: 4 helper (0-3) + 4 compute (4-7)
#define UPT    4            // hidden units per compute thread

__global__ __launch_bounds__(NTHR, 1)
void rate_rnn_scan_kernel(const float* __restrict__ x,
                          const float* __restrict__ Win,
                          const float* __restrict__ Wout,
                          const float* __restrict__ pin,
                          const float* __restrict__ pout,
                          const float* __restrict__ l,
                          float* __restrict__ out)
{
    const int b    = blockIdx.x;
    const int tid  = threadIdx.x;
    const int lane = tid & 31;
    const int wid  = tid >> 5;
    const bool is_comp = (wid >= 4);         // compute warps are hi-wid
    const int ctid = tid - 128;              // compute thread id 0..127
    const int cwid = wid - 4;                // compute warp 0..3
    const int half = lane >> 4;

    __shared__ float4 xs[TSTEPS + 1];                  // +1 pad for xs[t+1]
    __shared__ __align__(16) float4 rs[2][128];        // double-buffered r
    __shared__ __align__(16) float2 sp[2][8];          // s partials
    __shared__ __align__(16) float  yp[2][OUTDIM][8];  // y partials (helpers)

    const float4* x4 = reinterpret_cast<const float4*>(x);  // x: [T,B,4,1]
    for (int t = tid; t < TSTEPS; t += NTHR)
        xs[t] = x4[t * BATCH + b];
    if (tid == 0) xs[TSTEPS] = make_float4(0.f, 0.f, 0.f, 0.f);

    const float lm = 0.90483741803595952735f;   // exp(-dt/taum) = exp(-0.1)
    const float cc = 2.88539008177792681472f;   // 2*log2(e); state M = cc*mem
    const float oc = (1.0f - lm) * cc;

    // ---- per-role register state ----
    float4 wi[UPT];
    float  pi0[UPT], pi1[UPT], po0[UPT], po1[UPT];
    float  acc[UPT], M[UPT];
    float  wo0[UPT], wo1[UPT], wo2[UPT];
    float  s0 = 0.f, s1 = 0.f;

    if (is_comp) {
        const float l0 = l[0], l1 = l[1];
#pragma unroll
        for (int k = 0; k < UPT; ++k) {
            int h = ctid * UPT + k;
            float4 w = reinterpret_cast<const float4*>(Win)[h];
            wi[k] = make_float4(w.x * oc, w.y * oc, w.z * oc, w.w * oc);
            pi0[k] = pin[h * 2 + 0] * l0 * oc;
            pi1[k] = pin[h * 2 + 1] * l1 * oc;
            po0[k] = pout[h * 2 + 0];
            po1[k] = pout[h * 2 + 1];
            M[k] = 0.0f;
        }
    } else {
#pragma unroll
        for (int k = 0; k < UPT; ++k) {
            int h = tid * UPT + k;          // helper tid 0..127 mirrors ctid
            wo0[k] = Wout[h];
            wo1[k] = Wout[HID + h];
            wo2[k] = Wout[2 * HID + h];
        }
    }

    __syncthreads();   // xs staged

    if (is_comp) {     // prologue: acc for t=0 (M=0)
        float4 x0 = xs[0];
#pragma unroll
        for (int k = 0; k < UPT; ++k)
            acc[k] = fmaf(wi[k].w, x0.w, fmaf(wi[k].z, x0.z,
                     fmaf(wi[k].y, x0.y, wi[k].x * x0.x)));
    }

    int buf = 0;
    for (int t = 0; t < TSTEPS; ++t) {
        if (is_comp) {
            // ---- critical chain: s -> M -> tanh ----
            float r[UPT];
#pragma unroll
            for (int k = 0; k < UPT; ++k) {
                float m = fmaf(pi1[k], s1, fmaf(pi0[k], s0, acc[k]));
                M[k] = m;
                float e, rc;
                asm("ex2.approx.f32 %0, %1;" : "=f"(e)  : "f"(m));
                asm("rcp.approx.f32 %0, %1;" : "=f"(rc) : "f"(e + 1.0f));
                r[k] = fmaf(-2.0f, rc, 1.0f);
            }
            // export r for helper warps (off-chain; drained by the barrier)
            rs[buf][ctid] = make_float4(r[0], r[1], r[2], r[3]);

            // s-products + 8 shuffles (the only pre-barrier reduction work)
            float v = fmaf(po0[1], r[1], po0[0] * r[0]) + fmaf(po0[3], r[3], po0[2] * r[2]);
            float u = fmaf(po1[1], r[1], po1[0] * r[0]) + fmaf(po1[3], r[3], po1[2] * r[2]);
#pragma unroll
            for (int off = 1; off <= 8; off <<= 1) {
                v += __shfl_down_sync(0xffffffffu, v, off);
                u += __shfl_down_sync(0xffffffffu, u, off);
            }
            // next-step acc: independent of s; fills the shuffle-latency shadow
            float4 xtn = xs[t + 1];
#pragma unroll
            for (int k = 0; k < UPT; ++k) {
                float iin = fmaf(wi[k].w, xtn.w, fmaf(wi[k].z, xtn.z,
                            fmaf(wi[k].y, xtn.y, wi[k].x * xtn.x)));
                acc[k] = fmaf(lm, M[k], iin);
            }
            if ((lane & 15) == 0)
                sp[buf][cwid * 2 + half] = make_float2(v, u);
        }

        __syncthreads();   // single CTA barrier per step

        if (is_comp) {
            // 8 s-partials as 4 broadcast float4 loads + depth-3 tree
            const float4* q = reinterpret_cast<const float4*>(sp[buf]);
            float4 q0 = q[0], q1 = q[1], q2 = q[2], q3 = q[3];
            s0 = ((q0.x + q0.z) + (q1.x + q1.z)) + ((q2.x + q2.z) + (q3.x + q3.z));
            s1 = ((q0.y + q0.w) + (q1.y + q1.w)) + ((q2.y + q2.w) + (q3.y + q3.w));
        } else {
            // ---- helper warps: full y reduction, off the critical path ----
            float4 rv = rs[buf][tid];
            float y0 = fmaf(wo0[1], rv.y, wo0[0] * rv.x) + fmaf(wo0[3], rv.w, wo0[2] * rv.z);
            float y1 = fmaf(wo1[1], rv.y, wo1[0] * rv.x) + fmaf(wo1[3], rv.w, wo1[2] * rv.z);
            float y2 = fmaf(wo2[1], rv.y, wo2[0] * rv.x) + fmaf(wo2[3], rv.w, wo2[2] * rv.z);
#pragma unroll
            for (int off = 1; off <= 8; off <<= 1) {
                y0 += __shfl_down_sync(0xffffffffu, y0, off);
                y1 += __shfl_down_sync(0xffffffffu, y1, off);
                y2 += __shfl_down_sync(0xffffffffu, y2, off);
            }
            if ((lane & 15) == 0) {
                int slot = wid * 2 + half;
                yp[buf][0][slot] = y0;
                yp[buf][1][slot] = y1;
                yp[buf][2][slot] = y2;
            }
            asm volatile("bar.sync 1, 128;" ::: "memory");   // helpers only
            if (wid < OUTDIM && lane == 0) {
                const float4* p = reinterpret_cast<const float4*>(yp[buf][wid]);
                float4 a = p[0], c = p[1];
                float s = ((a.x + a.y) + (a.z + a.w)) + ((c.x + c.y) + (c.z + c.w));
                out[(t * BATCH + b) * OUTDIM + wid] = s;     // fire-and-forget
            }
        }
        buf ^= 1;
    }
}

extern "C" void kernel_launch(void* const* d_in, const int* in_sizes, int n_in,
                              void* d_out, int out_size)
{
    const float* x    = (const float*)d_in[0];  // [1000,64,4,1]
    const float* Win  = (const float*)d_in[1];  // [512,4]
    const float* Wout = (const float*)d_in[2];  // [3,512]
    const float* pin  = (const float*)d_in[3];  // [512,2]
    const float* pout = (const float*)d_in[4];  // [512,2]
    const float* l    = (const float*)d_in[5];  // [2]

    rate_rnn_scan_kernel<<<BATCH, NTHR>>>(x, Win, Wout, pin, pout, l,
                                          (float*)d_out);
}

// round 12
// speedup vs baseline: 1.3463x; 1.3463x over previous
#include <cuda_runtime.h>

// rate_RNN_mante: T=1000 sequential steps, B=64, IN=4, H=512, OUT=3.
// Wr = (l*pin) @ pout^T is rank-2 -> only two H-wide reductions (s0,s1) per
// step sit on the serial dependence chain.
//
// Scan kernel: one CTA per batch, 4 warps x 32 lanes x 4 hidden units.
// The loop contains ONLY the s-recurrence: tanh chain, po-products,
// 8 shuffles, STS partials, __syncthreads (4 warps), 4 broadcast LDS + tree.
// tanh values r are fire-and-forget STG.128'd to a global scratch; the
// output projection y = Wout @ r runs as a separate memory-bound kernel
// (64000 independent warp-rows). No helper warps, no named barriers.
// tanh = 1 - 2/(2^M+1), state pre-scaled by 2*log2(e) (EX2+RCP, ~1e-7 abs).

#define TSTEPS 1000
#define BATCH  64
#define HID    512
#define OUTDIM 3
#define NTHR   128          // 4 warps
#define UPT    4            // hidden units per thread
#define NROWS  (TSTEPS * BATCH)

// r scratch: [T*B][128] float4  (131 MB)
__device__ float4 g_r[NROWS * (HID / 4)];

__global__ __launch_bounds__(NTHR, 1)
void rate_rnn_scan_kernel(const float* __restrict__ x,
                          const float* __restrict__ Win,
                          const float* __restrict__ pin,
                          const float* __restrict__ pout,
                          const float* __restrict__ l)
{
    const int b    = blockIdx.x;
    const int tid  = threadIdx.x;
    const int lane = tid & 31;
    const int wid  = tid >> 5;
    const int half = lane >> 4;            // 0: lanes 0-15, 1: lanes 16-31
    const int slot = wid * 2 + half;       // 8 partial slots
    const bool writer = ((lane & 15) == 0);

    __shared__ float4 xs[TSTEPS + 1];             // staged input (+1 pad)
    __shared__ __align__(16) float2 sp[2][8];     // double-buffered s partials

    const float4* x4 = reinterpret_cast<const float4*>(x);  // x: [T,B,4,1]
    for (int t = tid; t < TSTEPS; t += NTHR)
        xs[t] = x4[t * BATCH + b];
    if (tid == 0) xs[TSTEPS] = make_float4(0.f, 0.f, 0.f, 0.f);

    const float lm = 0.90483741803595952735f;   // exp(-dt/taum) = exp(-0.1)
    const float cc = 2.88539008177792681472f;   // 2*log2(e); state M = cc*mem
    const float oc = (1.0f - lm) * cc;
    const float l0 = l[0], l1 = l[1];

    float4 wi[UPT];
    float  pi0[UPT], pi1[UPT], po0[UPT], po1[UPT];
    float  acc[UPT], M[UPT];
#pragma unroll
    for (int k = 0; k < UPT; ++k) {
        int h = tid * UPT + k;
        float4 w = reinterpret_cast<const float4*>(Win)[h];
        wi[k] = make_float4(w.x * oc, w.y * oc, w.z * oc, w.w * oc);
        pi0[k] = pin[h * 2 + 0] * l0 * oc;
        pi1[k] = pin[h * 2 + 1] * l1 * oc;
        po0[k] = pout[h * 2 + 0];
        po1[k] = pout[h * 2 + 1];
        M[k]   = 0.0f;
    }

    float s0 = 0.f, s1 = 0.f;       // pout^T tanh(mem_{t-1}); zero at t=0
    int buf = 0;

    float4* rrow = g_r + (size_t)b * (HID / 4) + tid;  // advance by B*128/step

    __syncthreads();   // xs staged

    {   // prologue: acc for t=0 (M = 0)
        float4 x0 = xs[0];
#pragma unroll
        for (int k = 0; k < UPT; ++k)
            acc[k] = fmaf(wi[k].w, x0.w, fmaf(wi[k].z, x0.z,
                     fmaf(wi[k].y, x0.y, wi[k].x * x0.x)));
    }

    for (int t = 0; t < TSTEPS; ++t) {
        // ---- critical chain: s -> M -> tanh ----
        float r[UPT];
#pragma unroll
        for (int k = 0; k < UPT; ++k) {
            float m = fmaf(pi1[k], s1, fmaf(pi0[k], s0, acc[k]));
            M[k] = m;
            float e, rc;
            asm("ex2.approx.f32 %0, %1;" : "=f"(e)  : "f"(m));
            asm("rcp.approx.f32 %0, %1;" : "=f"(rc) : "f"(e + 1.0f));
            r[k] = fmaf(-2.0f, rc, 1.0f);
        }

        // s-products + 8 shuffles: the only pre-barrier reduction work
        float v = fmaf(po0[1], r[1], po0[0] * r[0]) + fmaf(po0[3], r[3], po0[2] * r[2]);
        float u = fmaf(po1[1], r[1], po1[0] * r[0]) + fmaf(po1[3], r[3], po1[2] * r[2]);
#pragma unroll
        for (int off = 1; off <= 8; off <<= 1) {
            v += __shfl_down_sync(0xffffffffu, v, off);
            u += __shfl_down_sync(0xffffffffu, u, off);
        }

        // fire-and-forget r export + next-step acc: fill the shuffle shadow
        rrow[(size_t)t * (BATCH * (HID / 4))] = make_float4(r[0], r[1], r[2], r[3]);
        float4 xtn = xs[t + 1];
#pragma unroll
        for (int k = 0; k < UPT; ++k) {
            float iin = fmaf(wi[k].w, xtn.w, fmaf(wi[k].z, xtn.z,
                        fmaf(wi[k].y, xtn.y, wi[k].x * xtn.x)));
            acc[k] = fmaf(lm, M[k], iin);
        }

        if (writer) sp[buf][slot] = make_float2(v, u);
        __syncthreads();   // 4-warp barrier

        // 8 s-partials as 4 broadcast float4 loads + depth-3 tree
        const float4* q = reinterpret_cast<const float4*>(sp[buf]);
        float4 q0 = q[0], q1 = q[1], q2 = q[2], q3 = q[3];
        s0 = ((q0.x + q0.z) + (q1.x + q1.z)) + ((q2.x + q2.z) + (q3.x + q3.z));
        s1 = ((q0.y + q0.w) + (q1.y + q1.w)) + ((q2.y + q2.w) + (q3.y + q3.w));
        buf ^= 1;
    }
}

// y[row, o] = sum_h Wout[o,h] * r[row,h], row = t*BATCH + b. One warp per row.
__global__ __launch_bounds__(256, 4)
void project_y_kernel(const float* __restrict__ Wout, float* __restrict__ out)
{
    __shared__ __align__(16) float ws[OUTDIM * HID];   // 6 KB
    const int tid  = threadIdx.x;
    const int lane = tid & 31;
    const int wrp  = tid >> 5;

    for (int i = tid; i < OUTDIM * HID; i += 256)
        ws[i] = Wout[i];
    __syncthreads();

    const float4* ws4 = reinterpret_cast<const float4*>(ws);
    int row = blockIdx.x * 8 + wrp;                    // [0, 64000)
    const float4* rp = g_r + (size_t)row * (HID / 4);

    float y0 = 0.f, y1 = 0.f, y2 = 0.f;
#pragma unroll
    for (int j = 0; j < 4; ++j) {
        int idx = lane + 32 * j;                       // float4 index in row
        float4 rv = rp[idx];
        float4 a0 = ws4[0 * (HID / 4) + idx];
        float4 a1 = ws4[1 * (HID / 4) + idx];
        float4 a2 = ws4[2 * (HID / 4) + idx];
        y0 += fmaf(a0.w, rv.w, fmaf(a0.z, rv.z, fmaf(a0.y, rv.y, a0.x * rv.x)));
        y1 += fmaf(a1.w, rv.w, fmaf(a1.z, rv.z, fmaf(a1.y, rv.y, a1.x * rv.x)));
        y2 += fmaf(a2.w, rv.w, fmaf(a2.z, rv.z, fmaf(a2.y, rv.y, a2.x * rv.x)));
    }
#pragma unroll
    for (int off = 16; off >= 1; off >>= 1) {
        y0 += __shfl_xor_sync(0xffffffffu, y0, off);
        y1 += __shfl_xor_sync(0xffffffffu, y1, off);
        y2 += __shfl_xor_sync(0xffffffffu, y2, off);
    }
    if (lane == 0) {
        out[row * OUTDIM + 0] = y0;   // y: [T,B,OUT,1] -> row-major rows
        out[row * OUTDIM + 1] = y1;
        out[row * OUTDIM + 2] = y2;
    }
}

extern "C" void kernel_launch(void* const* d_in, const int* in_sizes, int n_in,
                              void* d_out, int out_size)
{
    const float* x    = (const float*)d_in[0];  // [1000,64,4,1]
    const float* Win  = (const float*)d_in[1];  // [512,4]
    const float* Wout = (const float*)d_in[2];  // [3,512]
    const float* pin  = (const float*)d_in[3];  // [512,2]
    const float* pout = (const float*)d_in[4];  // [512,2]
    const float* l    = (const float*)d_in[5];  // [2]

    rate_rnn_scan_kernel<<<BATCH, NTHR>>>(x, Win, pin, pout, l);
    project_y_kernel<<<NROWS / 8, 256>>>(Wout, (float*)d_out);
}